// round 14
// baseline (speedup 1.0000x reference)
#include <cuda_runtime.h>
#include <cuda_bf16.h>
#include <cuda_fp16.h>
#include <cstdint>

#define B_      8
#define N_      2048
#define PATCH_  768
#define POS_    64
#define DIN_    832
#define HID_    512
#define M_TOT   (B_ * N_)
#define SCALE_  0.04419417382415922f

// smem tile geometry: CTA tile 256x128, warp tile 64x64 (8 warps, 4x2)
#define LDA_B    80                     // padded row bytes (64 data + 16 pad)
#define LDV_B    272                    // padded row for 128-wide V tile
#define TILE_A_B 20480                  // 256 * 80  (A/E tile, 256 rows)
#define TILE_B_B 10240                  // 128 * 80  (B tile, 128 rows)
#define TILE_V_B 8704                   // 32 * 272  (V tile, KN layout)
#define STAGE_KK (TILE_A_B + TILE_B_B)  // 30720
#define STAGE_AV (TILE_A_B + TILE_V_B)  // 29184
#define NSTAGE   3
#define SMEM_KK  (NSTAGE * STAGE_KK)    // 92160
#define SMEM_AV  (NSTAGE * STAGE_AV)    // 87552

// ---------------- scratch (static device memory; no allocations) ------------
__device__ __align__(16) half  g_X[(size_t)M_TOT * DIN_];           // fp16 concat input
__device__ __align__(16) half  g_Wt[(size_t)3 * HID_ * DIN_];       // fp16 W^T [w][n][k]
__device__ __align__(16) half  g_Q[(size_t)M_TOT * HID_];
__device__ __align__(16) half  g_K[(size_t)M_TOT * HID_];
__device__ __align__(16) half  g_V[(size_t)M_TOT * HID_];
__device__ __align__(16) half  g_E[(size_t)B_ * N_ * N_];           // exp(scores), fp16
__device__ __align__(16) float g_Rsum[(size_t)M_TOT];               // row sums (atomic)

// ---------------- PTX helpers ------------------------------------------------
__device__ __forceinline__ uint32_t smem_u32(const void* p) {
    uint32_t a;
    asm("{ .reg .u64 t; cvta.to.shared.u64 t, %1; cvt.u32.u64 %0, t; }" : "=r"(a) : "l"(p));
    return a;
}
__device__ __forceinline__ void cp16(uint32_t dst, const void* src) {
    asm volatile("cp.async.cg.shared.global [%0], [%1], 16;"
                 :: "r"(dst), "l"(__cvta_generic_to_global(src)));
}
#define CP_COMMIT() asm volatile("cp.async.commit_group;" ::: "memory")
#define CP_WAIT1()  asm volatile("cp.async.wait_group 1;" ::: "memory")
#define CP_WAIT0()  asm volatile("cp.async.wait_group 0;" ::: "memory")

__device__ __forceinline__ void ldm_x4(uint32_t* r, uint32_t addr) {
    asm volatile("ldmatrix.sync.aligned.m8n8.x4.shared.b16 {%0,%1,%2,%3}, [%4];"
                 : "=r"(r[0]), "=r"(r[1]), "=r"(r[2]), "=r"(r[3]) : "r"(addr));
}
__device__ __forceinline__ void ldm_x4t(uint32_t* r, uint32_t addr) {
    asm volatile("ldmatrix.sync.aligned.m8n8.x4.trans.shared.b16 {%0,%1,%2,%3}, [%4];"
                 : "=r"(r[0]), "=r"(r[1]), "=r"(r[2]), "=r"(r[3]) : "r"(addr));
}
__device__ __forceinline__ void mma_f16(float* c, const uint32_t* a, const uint32_t* b) {
    asm volatile("mma.sync.aligned.m16n8k16.row.col.f32.f16.f16.f32 "
                 "{%0,%1,%2,%3}, {%4,%5,%6,%7}, {%8,%9}, {%0,%1,%2,%3};"
                 : "+f"(c[0]), "+f"(c[1]), "+f"(c[2]), "+f"(c[3])
                 : "r"(a[0]), "r"(a[1]), "r"(a[2]), "r"(a[3]), "r"(b[0]), "r"(b[1]));
}
__device__ __forceinline__ uint32_t pk2h(half a, half b) {
    return (uint32_t)__half_as_ushort(a) | ((uint32_t)__half_as_ushort(b) << 16);
}

// ---------------- stage loaders (256 threads) ---------------------------------
// kk: A[256][32] + B[128][32], fp16 single, both K-major
__device__ __forceinline__ void load_stage_kk(uint32_t sb,
        const half* gA, const half* gB, int ldA, int ldB, int k0, int tid) {
    #pragma unroll
    for (int r = 0; r < 4; r++) {          // A: 256 rows * 4 segs = 1024
        int i = tid + 256 * r;
        int row = i >> 2, seg = i & 3;
        cp16(sb + (uint32_t)(row * LDA_B + seg * 16),
             gA + (size_t)row * ldA + k0 + seg * 8);
    }
    #pragma unroll
    for (int r = 0; r < 2; r++) {          // B: 128 rows * 4 segs = 512
        int i = tid + 256 * r;
        int row = i >> 2, seg = i & 3;
        cp16(sb + TILE_A_B + (uint32_t)(row * LDA_B + seg * 16),
             gB + (size_t)row * ldB + k0 + seg * 8);
    }
}

// av: E[256][32] (K-major) + V[32][128] (KN layout)
__device__ __forceinline__ void load_stage_av(uint32_t sb,
        const half* gA, const half* gB, int ldA, int ldB, int k0, int tid) {
    #pragma unroll
    for (int r = 0; r < 4; r++) {
        int i = tid + 256 * r;
        int row = i >> 2, seg = i & 3;
        cp16(sb + (uint32_t)(row * LDA_B + seg * 16),
             gA + (size_t)row * ldA + k0 + seg * 8);
    }
    #pragma unroll
    for (int r = 0; r < 2; r++) {          // V: 32 rows * 16 segs = 512
        int i = tid + 256 * r;
        int row = i >> 4, seg = i & 15;
        cp16(sb + TILE_A_B + (uint32_t)(row * LDV_B + seg * 16),
             gB + (size_t)(k0 + row) * ldB + seg * 8);
    }
}

// ---------------- compute: one K=32 chunk, 64x64 warp tile, fp16 -------------
// warp_m in 0..3 (64 M-rows each of 256), warp_n in 0..1 (64 N-cols of 128).
__device__ __forceinline__ void compute_chunk_kk(uint32_t sb, int warp_m, int warp_n,
                                                 int lane, float acc[4][8][4]) {
    const int g = lane >> 3;
    uint32_t a[2][4][4], b[2][4][4];
    #pragma unroll
    for (int ks = 0; ks < 2; ks++) {
        const int kc = ks * 16;
        #pragma unroll
        for (int i = 0; i < 4; i++) {
            uint32_t addr = sb + (uint32_t)((warp_m * 64 + i * 16 + (lane & 15)) * LDA_B
                                            + (kc + (lane >> 4) * 8) * 2);
            ldm_x4(a[ks][i], addr);
        }
        #pragma unroll
        for (int jj = 0; jj < 4; jj++) {
            int brow = warp_n * 64 + jj * 16 + ((g & 2) ? 8 : 0) + (lane & 7);
            int bcol = kc + (g & 1) * 8;
            ldm_x4(b[ks][jj], sb + TILE_A_B + (uint32_t)(brow * LDA_B + bcol * 2));
        }
    }
    #pragma unroll
    for (int ks = 0; ks < 2; ks++)
        #pragma unroll
        for (int jj = 0; jj < 4; jj++)
            #pragma unroll
            for (int i = 0; i < 4; i++) {
                mma_f16(acc[i][jj * 2],     a[ks][i], b[ks][jj]);
                mma_f16(acc[i][jj * 2 + 1], a[ks][i], b[ks][jj] + 2);
            }
}

// av: B in KN layout (trans ldmatrix)
__device__ __forceinline__ void compute_chunk_av(uint32_t sb, int warp_m, int warp_n,
                                                 int lane, float acc[4][8][4]) {
    const int g = lane >> 3;
    uint32_t a[2][4][4], b[2][4][4];
    #pragma unroll
    for (int ks = 0; ks < 2; ks++) {
        const int kc = ks * 16;
        #pragma unroll
        for (int i = 0; i < 4; i++) {
            uint32_t addr = sb + (uint32_t)((warp_m * 64 + i * 16 + (lane & 15)) * LDA_B
                                            + (kc + (lane >> 4) * 8) * 2);
            ldm_x4(a[ks][i], addr);
        }
        #pragma unroll
        for (int jj = 0; jj < 4; jj++) {
            int brow = kc + (g & 1) * 8 + (lane & 7);
            int bcol = warp_n * 64 + jj * 16 + ((g & 2) ? 8 : 0);
            ldm_x4t(b[ks][jj], sb + TILE_A_B + (uint32_t)(brow * LDV_B + bcol * 2));
        }
    }
    #pragma unroll
    for (int ks = 0; ks < 2; ks++)
        #pragma unroll
        for (int jj = 0; jj < 4; jj++)
            #pragma unroll
            for (int i = 0; i < 4; i++) {
                mma_f16(acc[i][jj * 2],     a[ks][i], b[ks][jj]);
                mma_f16(acc[i][jj * 2 + 1], a[ks][i], b[ks][jj] + 2);
            }
}

#define ACC_ZERO(acc)                                   \
    _Pragma("unroll")                                   \
    for (int _i = 0; _i < 4; _i++)                      \
        _Pragma("unroll")                               \
        for (int _j = 0; _j < 8; _j++)                  \
            _Pragma("unroll")                           \
            for (int _r = 0; _r < 4; _r++) acc[_i][_j][_r] = 0.0f;

// 3-stage ring mainloop (one __syncthreads per chunk, loads before compute)
#define PIPE3(NC, LOADFN, CHUNKFN, STAGE, ldA, ldB)                           \
    LOADFN(sb, gA, gB, ldA, ldB, 0, tid);                                     \
    CP_COMMIT();                                                              \
    LOADFN(sb + STAGE, gA, gB, ldA, ldB, 32, tid);                            \
    CP_COMMIT();                                                              \
    int slot = 0;                                                             \
    _Pragma("unroll 1")                                                       \
    for (int c = 0; c < (NC); c++) {                                          \
        if (c < (NC) - 1) CP_WAIT1(); else CP_WAIT0();                        \
        __syncthreads();                                                      \
        if (c + 2 < (NC)) {                                                   \
            int ns = slot + 2; if (ns >= NSTAGE) ns -= NSTAGE;                \
            LOADFN(sb + ns * STAGE, gA, gB, ldA, ldB, (c + 2) * 32, tid);     \
        }                                                                     \
        CP_COMMIT();                                                          \
        CHUNKFN(sb + slot * STAGE, warp_m, warp_n, lane, acc);                \
        if (++slot == NSTAGE) slot = 0;                                       \
    }

// ---------------- prep: fp16 X = concat(patches, positions) ------------------
__global__ void xsplit_kernel(const float* __restrict__ patches,
                              const float* __restrict__ positions) {
    const size_t m = blockIdx.x;
    const int t = threadIdx.x;  // 208 threads, 4 elems each
    const float* src = (t < 192) ? patches + m * PATCH_ + t * 4
                                 : positions + m * POS_ + (t - 192) * 4;
    float4 v = *(const float4*)src;
    uint2 hh = make_uint2(pk2h(__float2half(v.x), __float2half(v.y)),
                          pk2h(__float2half(v.z), __float2half(v.w)));
    *(uint2*)&g_X[m * DIN_ + t * 4] = hh;
}

// ---------------- prep: transpose weights to fp16; zero row sums -------------
__global__ void wsplit_kernel(const float* __restrict__ Wq,
                              const float* __restrict__ Wk,
                              const float* __restrict__ Wv) {
    __shared__ float s[32][33];
    const int which = blockIdx.z;
    const float* W = (which == 0) ? Wq : (which == 1) ? Wk : Wv;
    const int n0 = blockIdx.x * 32;
    const int k0 = blockIdx.y * 32;
    s[threadIdx.y][threadIdx.x] = W[(size_t)(k0 + threadIdx.y) * HID_ + n0 + threadIdx.x];
    __syncthreads();
    float v = s[threadIdx.x][threadIdx.y];
    size_t o = ((size_t)which * HID_ + n0 + threadIdx.y) * DIN_ + k0 + threadIdx.x;
    g_Wt[o] = __float2half(v);
}

__global__ void zero_rsum_kernel() {
    g_Rsum[blockIdx.x * 256 + threadIdx.x] = 0.0f;
}

// ---------------- kernel 1: QKV projection (fp16, 256x128 tile) --------------
__global__ __launch_bounds__(256, 1)
void qkv_kernel(const float* __restrict__ bq, const float* __restrict__ bk,
                const float* __restrict__ bv) {
    extern __shared__ char smem[];
    uint32_t sb = smem_u32(smem);
    const int tid = threadIdx.x, lane = tid & 31, wid = tid >> 5;
    const int warp_m = wid & 3, warp_n = wid >> 2;
    const int which = blockIdx.z;
    const size_t m0 = (size_t)blockIdx.x * 256;
    const int n0 = blockIdx.y * 128;

    const half* gA = g_X + m0 * DIN_;
    const half* gB = g_Wt + ((size_t)which * HID_ + n0) * DIN_;

    float acc[4][8][4];
    ACC_ZERO(acc);

    PIPE3(DIN_ / 32, load_stage_kk, compute_chunk_kk, STAGE_KK, DIN_, DIN_);

    const float* bias = (which == 0) ? bq : (which == 1) ? bk : bv;
    half* dst = (which == 0) ? g_Q : (which == 1) ? g_K : g_V;
    #pragma unroll
    for (int i = 0; i < 4; i++)
        #pragma unroll
        for (int j = 0; j < 8; j++) {
            int row = warp_m * 64 + i * 16 + (lane >> 2);
            int col = n0 + warp_n * 64 + j * 8 + (lane & 3) * 2;
            float b0 = bias[col], b1 = bias[col + 1];
            #pragma unroll
            for (int h = 0; h < 2; h++) {
                size_t r = m0 + row + h * 8;
                *(uint32_t*)&dst[r * HID_ + col] =
                    pk2h(__float2half(acc[i][j][h * 2] + b0),
                         __float2half(acc[i][j][h * 2 + 1] + b1));
            }
        }
}

// ---------------- kernel 2: E = exp(QK^T*scale) + fused row sums -------------
__global__ __launch_bounds__(256, 1)
void score_kernel() {
    extern __shared__ char smem[];
    uint32_t sb = smem_u32(smem);
    const int tid = threadIdx.x, lane = tid & 31, wid = tid >> 5;
    const int warp_m = wid & 3, warp_n = wid >> 2;
    const int b = blockIdx.z;
    const size_t m0 = (size_t)b * N_ + blockIdx.x * 256;
    const size_t n0 = (size_t)b * N_ + blockIdx.y * 128;

    const half* gA = g_Q + m0 * HID_;
    const half* gB = g_K + n0 * HID_;

    float acc[4][8][4];
    ACC_ZERO(acc);

    PIPE3(HID_ / 32, load_stage_kk, compute_chunk_kk, STAGE_KK, HID_, HID_);

    float rsum[4][2];
    #pragma unroll
    for (int i = 0; i < 4; i++) { rsum[i][0] = 0.0f; rsum[i][1] = 0.0f; }

    #pragma unroll
    for (int i = 0; i < 4; i++)
        #pragma unroll
        for (int j = 0; j < 8; j++) {
            int row = blockIdx.x * 256 + warp_m * 64 + i * 16 + (lane >> 2);
            int col = blockIdx.y * 128 + warp_n * 64 + j * 8 + (lane & 3) * 2;
            #pragma unroll
            for (int h = 0; h < 2; h++) {
                float e0 = __expf(acc[i][j][h * 2] * SCALE_);
                float e1 = __expf(acc[i][j][h * 2 + 1] * SCALE_);
                size_t off = ((size_t)b * N_ + row + h * 8) * N_ + col;
                *(uint32_t*)&g_E[off] = pk2h(__float2half(e0), __float2half(e1));
                rsum[i][h] += e0 + e1;
            }
        }

    // quad reduce (lanes sharing a row differ in lane&3), then atomic add
    #pragma unroll
    for (int i = 0; i < 4; i++)
        #pragma unroll
        for (int h = 0; h < 2; h++) {
            float s = rsum[i][h];
            s += __shfl_xor_sync(0xffffffffu, s, 1);
            s += __shfl_xor_sync(0xffffffffu, s, 2);
            if ((lane & 3) == 0) {
                size_t r = (size_t)b * N_ + blockIdx.x * 256
                         + warp_m * 64 + i * 16 + (lane >> 2) + h * 8;
                atomicAdd(&g_Rsum[r], s);
            }
        }
}

// ---------------- kernel 3: O = (E V) / rowsum -------------------------------
__global__ __launch_bounds__(256, 1)
void av_kernel(float* __restrict__ out) {
    extern __shared__ char smem[];
    uint32_t sb = smem_u32(smem);
    const int tid = threadIdx.x, lane = tid & 31, wid = tid >> 5;
    const int warp_m = wid & 3, warp_n = wid >> 2;
    const int b = blockIdx.z;
    const int n0 = blockIdx.y * 128;

    const half* gA = g_E + ((size_t)b * N_ + blockIdx.x * 256) * N_;
    const half* gB = g_V + ((size_t)b * N_) * HID_ + n0;   // rows = tokens(k)

    float acc[4][8][4];
    ACC_ZERO(acc);

    PIPE3(N_ / 32, load_stage_av, compute_chunk_av, STAGE_AV, N_, HID_);

    float rinv[4][2];
    #pragma unroll
    for (int i = 0; i < 4; i++)
        #pragma unroll
        for (int h = 0; h < 2; h++) {
            size_t r = (size_t)b * N_ + blockIdx.x * 256
                     + warp_m * 64 + i * 16 + (lane >> 2) + h * 8;
            rinv[i][h] = 1.0f / g_Rsum[r];
        }

    #pragma unroll
    for (int i = 0; i < 4; i++)
        #pragma unroll
        for (int j = 0; j < 8; j++) {
            int row = blockIdx.x * 256 + warp_m * 64 + i * 16 + (lane >> 2);
            int col = n0 + warp_n * 64 + j * 8 + (lane & 3) * 2;
            #pragma unroll
            for (int h = 0; h < 2; h++) {
                size_t off = ((size_t)b * N_ + row + h * 8) * HID_ + col;
                float2 v = make_float2(acc[i][j][h * 2] * rinv[i][h],
                                       acc[i][j][h * 2 + 1] * rinv[i][h]);
                *(float2*)&out[off] = v;
            }
        }
}

// ---------------- launcher ---------------------------------------------------
extern "C" void kernel_launch(void* const* d_in, const int* in_sizes, int n_in,
                              void* d_out, int out_size) {
    const float* patches   = (const float*)d_in[0];
    const float* positions = (const float*)d_in[1];
    const float* Wq = (const float*)d_in[2];
    const float* bq = (const float*)d_in[3];
    const float* Wk = (const float*)d_in[4];
    const float* bk = (const float*)d_in[5];
    const float* Wv = (const float*)d_in[6];
    const float* bv = (const float*)d_in[7];
    float* out = (float*)d_out;

    cudaFuncSetAttribute(qkv_kernel,   cudaFuncAttributeMaxDynamicSharedMemorySize, SMEM_KK);
    cudaFuncSetAttribute(score_kernel, cudaFuncAttributeMaxDynamicSharedMemorySize, SMEM_KK);
    cudaFuncSetAttribute(av_kernel,    cudaFuncAttributeMaxDynamicSharedMemorySize, SMEM_AV);

    dim3 gw(HID_ / 32, DIN_ / 32, 3);  // 16 x 26 x 3
    wsplit_kernel<<<gw, dim3(32, 32)>>>(Wq, Wk, Wv);

    xsplit_kernel<<<M_TOT, 208>>>(patches, positions);
    zero_rsum_kernel<<<M_TOT / 256, 256>>>();

    dim3 g1(M_TOT / 256, HID_ / 128, 3);  // 64 x 4 x 3
    qkv_kernel<<<g1, 256, SMEM_KK>>>(bq, bk, bv);

    dim3 g2(N_ / 256, N_ / 128, B_);      // 8 x 16 x 8
    score_kernel<<<g2, 256, SMEM_KK>>>();

    dim3 g3(N_ / 256, HID_ / 128, B_);    // 8 x 4 x 8
    av_kernel<<<g3, 256, SMEM_AV>>>(out);
}

// round 15
// speedup vs baseline: 1.2785x; 1.2785x over previous
#include <cuda_runtime.h>
#include <cuda_bf16.h>
#include <cuda_fp16.h>
#include <cstdint>

#define B_      8
#define N_      2048
#define PATCH_  768
#define POS_    64
#define DIN_    832
#define HID_    512
#define M_TOT   (B_ * N_)
#define SCALE_  0.04419417382415922f

// smem tile geometry: CTA tile 128x128, warp tile 64x64 (4 warps, 2x2)
#define LDA_B   80                      // padded row bytes (64 data + 16 pad)
#define LDV_B   272                     // padded row for 128-wide V tile
#define TILE_A_B 10240                  // 128 * 80
#define TILE_V_B 8704                   // 32 * 272
#define STAGE_KK (2 * TILE_A_B)         // 20480: A tile + B tile (fp16, K-major)
#define STAGE_AV (TILE_A_B + TILE_V_B)  // 18944: E tile + V tile
#define NSTAGE  3
#define SMEM_KK (NSTAGE * STAGE_KK)     // 61440 -> 2 CTAs/SM
#define SMEM_AV (NSTAGE * STAGE_AV)     // 56832 -> 2 CTAs/SM

// ---------------- scratch (static device memory; no allocations) ------------
__device__ __align__(16) half  g_X[(size_t)M_TOT * DIN_];           // fp16 concat input
__device__ __align__(16) half  g_Wt[(size_t)3 * HID_ * DIN_];       // fp16 W^T [w][n][k]
__device__ __align__(16) half  g_Q[(size_t)M_TOT * HID_];
__device__ __align__(16) half  g_K[(size_t)M_TOT * HID_];
__device__ __align__(16) half  g_V[(size_t)M_TOT * HID_];
__device__ __align__(16) half  g_E[(size_t)B_ * N_ * N_];           // exp(scores), fp16
__device__ __align__(16) float g_Rsum[(size_t)M_TOT];               // row sums (atomic)

// ---------------- PTX helpers ------------------------------------------------
__device__ __forceinline__ uint32_t smem_u32(const void* p) {
    uint32_t a;
    asm("{ .reg .u64 t; cvta.to.shared.u64 t, %1; cvt.u32.u64 %0, t; }" : "=r"(a) : "l"(p));
    return a;
}
__device__ __forceinline__ void cp16(uint32_t dst, const void* src) {
    asm volatile("cp.async.cg.shared.global [%0], [%1], 16;"
                 :: "r"(dst), "l"(__cvta_generic_to_global(src)));
}
#define CP_COMMIT() asm volatile("cp.async.commit_group;" ::: "memory")
#define CP_WAIT1()  asm volatile("cp.async.wait_group 1;" ::: "memory")
#define CP_WAIT0()  asm volatile("cp.async.wait_group 0;" ::: "memory")

__device__ __forceinline__ void ldm_x4(uint32_t* r, uint32_t addr) {
    asm volatile("ldmatrix.sync.aligned.m8n8.x4.shared.b16 {%0,%1,%2,%3}, [%4];"
                 : "=r"(r[0]), "=r"(r[1]), "=r"(r[2]), "=r"(r[3]) : "r"(addr));
}
__device__ __forceinline__ void ldm_x4t(uint32_t* r, uint32_t addr) {
    asm volatile("ldmatrix.sync.aligned.m8n8.x4.trans.shared.b16 {%0,%1,%2,%3}, [%4];"
                 : "=r"(r[0]), "=r"(r[1]), "=r"(r[2]), "=r"(r[3]) : "r"(addr));
}
__device__ __forceinline__ void mma_f16(float* c, const uint32_t* a, const uint32_t* b) {
    asm volatile("mma.sync.aligned.m16n8k16.row.col.f32.f16.f16.f32 "
                 "{%0,%1,%2,%3}, {%4,%5,%6,%7}, {%8,%9}, {%0,%1,%2,%3};"
                 : "+f"(c[0]), "+f"(c[1]), "+f"(c[2]), "+f"(c[3])
                 : "r"(a[0]), "r"(a[1]), "r"(a[2]), "r"(a[3]), "r"(b[0]), "r"(b[1]));
}
__device__ __forceinline__ uint32_t pk2h(half a, half b) {
    return (uint32_t)__half_as_ushort(a) | ((uint32_t)__half_as_ushort(b) << 16);
}

// ---------------- stage loaders (128 threads) ---------------------------------
// kk: A[128][32] + B[128][32], fp16 single, both K-major
__device__ __forceinline__ void load_stage_kk(uint32_t sb,
        const half* gA, const half* gB, int ldA, int ldB, int k0, int tid) {
    #pragma unroll
    for (int r = 0; r < 4; r++) {
        int i = tid + 128 * r;   // 0..511
        int row = i >> 2, seg = i & 3;
        uint32_t doff = (uint32_t)(row * LDA_B + seg * 16);
        cp16(sb + doff,            gA + (size_t)row * ldA + k0 + seg * 8);
        cp16(sb + TILE_A_B + doff, gB + (size_t)row * ldB + k0 + seg * 8);
    }
}

// av: E[128][32] (K-major) + V[32][128] (KN layout)
__device__ __forceinline__ void load_stage_av(uint32_t sb,
        const half* gA, const half* gB, int ldA, int ldB, int k0, int tid) {
    #pragma unroll
    for (int r = 0; r < 4; r++) {
        int i = tid + 128 * r;
        {
            int row = i >> 2, seg = i & 3;
            cp16(sb + (uint32_t)(row * LDA_B + seg * 16),
                 gA + (size_t)row * ldA + k0 + seg * 8);
        }
        {
            int row = i >> 4, seg = i & 15;  // row 0..31
            cp16(sb + TILE_A_B + (uint32_t)(row * LDV_B + seg * 16),
                 gB + (size_t)(k0 + row) * ldB + seg * 8);
        }
    }
}

// ---------------- compute: one K=32 chunk, 64x64 warp tile, fp16 -------------
// All 16 fragment loads issued back-to-back (MLP covers LDS latency) before
// the 64-MMA burst.
__device__ __forceinline__ void compute_chunk_kk(uint32_t sb, int warp_m, int warp_n,
                                                 int lane, float acc[4][8][4]) {
    const int g = lane >> 3;
    uint32_t a[2][4][4], b[2][4][4];
    #pragma unroll
    for (int ks = 0; ks < 2; ks++) {
        const int kc = ks * 16;
        #pragma unroll
        for (int i = 0; i < 4; i++) {
            uint32_t addr = sb + (uint32_t)((warp_m * 64 + i * 16 + (lane & 15)) * LDA_B
                                            + (kc + (lane >> 4) * 8) * 2);
            ldm_x4(a[ks][i], addr);
        }
        #pragma unroll
        for (int jj = 0; jj < 4; jj++) {
            int brow = warp_n * 64 + jj * 16 + ((g & 2) ? 8 : 0) + (lane & 7);
            int bcol = kc + (g & 1) * 8;
            ldm_x4(b[ks][jj], sb + TILE_A_B + (uint32_t)(brow * LDA_B + bcol * 2));
        }
    }
    #pragma unroll
    for (int ks = 0; ks < 2; ks++)
        #pragma unroll
        for (int jj = 0; jj < 4; jj++)
            #pragma unroll
            for (int i = 0; i < 4; i++) {
                mma_f16(acc[i][jj * 2],     a[ks][i], b[ks][jj]);
                mma_f16(acc[i][jj * 2 + 1], a[ks][i], b[ks][jj] + 2);
            }
}

// av: B in KN layout (trans ldmatrix)
__device__ __forceinline__ void compute_chunk_av(uint32_t sb, int warp_m, int warp_n,
                                                 int lane, float acc[4][8][4]) {
    const int g = lane >> 3;
    uint32_t a[2][4][4], b[2][4][4];
    #pragma unroll
    for (int ks = 0; ks < 2; ks++) {
        const int kc = ks * 16;
        #pragma unroll
        for (int i = 0; i < 4; i++) {
            uint32_t addr = sb + (uint32_t)((warp_m * 64 + i * 16 + (lane & 15)) * LDA_B
                                            + (kc + (lane >> 4) * 8) * 2);
            ldm_x4(a[ks][i], addr);
        }
        #pragma unroll
        for (int jj = 0; jj < 4; jj++) {
            int brow = kc + (g & 1) * 8 + (lane & 7);
            int bcol = warp_n * 64 + jj * 16 + ((g & 2) ? 8 : 0);
            ldm_x4t(b[ks][jj], sb + TILE_A_B + (uint32_t)(brow * LDV_B + bcol * 2));
        }
    }
    #pragma unroll
    for (int ks = 0; ks < 2; ks++)
        #pragma unroll
        for (int jj = 0; jj < 4; jj++)
            #pragma unroll
            for (int i = 0; i < 4; i++) {
                mma_f16(acc[i][jj * 2],     a[ks][i], b[ks][jj]);
                mma_f16(acc[i][jj * 2 + 1], a[ks][i], b[ks][jj] + 2);
            }
}

#define ACC_ZERO(acc)                                   \
    _Pragma("unroll")                                   \
    for (int _i = 0; _i < 4; _i++)                      \
        _Pragma("unroll")                               \
        for (int _j = 0; _j < 8; _j++)                  \
            _Pragma("unroll")                           \
            for (int _r = 0; _r < 4; _r++) acc[_i][_j][_r] = 0.0f;

// ---------------- prep: fp16 X = concat(patches, positions) ------------------
__global__ void xsplit_kernel(const float* __restrict__ patches,
                              const float* __restrict__ positions) {
    const size_t m = blockIdx.x;
    const int t = threadIdx.x;  // 208 threads, 4 elems each
    const float* src = (t < 192) ? patches + m * PATCH_ + t * 4
                                 : positions + m * POS_ + (t - 192) * 4;
    float4 v = *(const float4*)src;
    uint2 hh = make_uint2(pk2h(__float2half(v.x), __float2half(v.y)),
                          pk2h(__float2half(v.z), __float2half(v.w)));
    *(uint2*)&g_X[m * DIN_ + t * 4] = hh;
}

// ---------------- prep: transpose weights to fp16 ----------------------------
__global__ void wsplit_kernel(const float* __restrict__ Wq,
                              const float* __restrict__ Wk,
                              const float* __restrict__ Wv) {
    __shared__ float s[32][33];
    const int which = blockIdx.z;
    const float* W = (which == 0) ? Wq : (which == 1) ? Wk : Wv;
    const int n0 = blockIdx.x * 32;
    const int k0 = blockIdx.y * 32;
    s[threadIdx.y][threadIdx.x] = W[(size_t)(k0 + threadIdx.y) * HID_ + n0 + threadIdx.x];
    __syncthreads();
    float v = s[threadIdx.x][threadIdx.y];
    size_t o = ((size_t)which * HID_ + n0 + threadIdx.y) * DIN_ + k0 + threadIdx.x;
    g_Wt[o] = __float2half(v);
}

__global__ void zero_rsum_kernel() {
    g_Rsum[blockIdx.x * 256 + threadIdx.x] = 0.0f;
}

// ---------------- kernel 1: QKV projection (fp16 single product) -------------
__global__ __launch_bounds__(128, 2)
void qkv_kernel(const float* __restrict__ bq, const float* __restrict__ bk,
                const float* __restrict__ bv) {
    extern __shared__ char smem[];
    uint32_t sb = smem_u32(smem);
    const int tid = threadIdx.x, lane = tid & 31, wid = tid >> 5;
    const int warp_m = wid & 1, warp_n = wid >> 1;
    const int which = blockIdx.z;
    const size_t m0 = (size_t)blockIdx.x * 128;
    const int n0 = blockIdx.y * 128;

    const half* gA = g_X + m0 * DIN_;
    const half* gB = g_Wt + ((size_t)which * HID_ + n0) * DIN_;

    float acc[4][8][4];
    ACC_ZERO(acc);

    {
        const int NC = DIN_ / 32;  // 26
        load_stage_kk(sb, gA, gB, DIN_, DIN_, 0, tid);
        CP_COMMIT();
        load_stage_kk(sb + STAGE_KK, gA, gB, DIN_, DIN_, 32, tid);
        CP_COMMIT();
        int slot = 0;
        #pragma unroll 1
        for (int c = 0; c < NC; c++) {
            if (c < NC - 1) CP_WAIT1(); else CP_WAIT0();
            __syncthreads();
            if (c + 2 < NC) {
                int ns = slot + 2; if (ns >= NSTAGE) ns -= NSTAGE;
                load_stage_kk(sb + ns * STAGE_KK, gA, gB, DIN_, DIN_,
                              (c + 2) * 32, tid);
            }
            CP_COMMIT();
            compute_chunk_kk(sb + slot * STAGE_KK, warp_m, warp_n, lane, acc);
            if (++slot == NSTAGE) slot = 0;
        }
    }

    const float* bias = (which == 0) ? bq : (which == 1) ? bk : bv;
    half* dst = (which == 0) ? g_Q : (which == 1) ? g_K : g_V;
    #pragma unroll
    for (int i = 0; i < 4; i++)
        #pragma unroll
        for (int j = 0; j < 8; j++) {
            int row = warp_m * 64 + i * 16 + (lane >> 2);
            int col = n0 + warp_n * 64 + j * 8 + (lane & 3) * 2;
            float b0 = bias[col], b1 = bias[col + 1];
            #pragma unroll
            for (int h = 0; h < 2; h++) {
                size_t r = m0 + row + h * 8;
                *(uint32_t*)&dst[r * HID_ + col] =
                    pk2h(__float2half(acc[i][j][h * 2] + b0),
                         __float2half(acc[i][j][h * 2 + 1] + b1));
            }
        }
}

// ---------------- kernel 2: E = exp(QK^T*scale), fp16 + fused row sums -------
__global__ __launch_bounds__(128, 2)
void score_kernel() {
    extern __shared__ char smem[];
    uint32_t sb = smem_u32(smem);
    const int tid = threadIdx.x, lane = tid & 31, wid = tid >> 5;
    const int warp_m = wid & 1, warp_n = wid >> 1;
    const int b = blockIdx.z;
    const size_t m0 = (size_t)b * N_ + blockIdx.x * 128;
    const size_t n0 = (size_t)b * N_ + blockIdx.y * 128;

    const half* gA = g_Q + m0 * HID_;
    const half* gB = g_K + n0 * HID_;

    float acc[4][8][4];
    ACC_ZERO(acc);

    {
        const int NC = HID_ / 32;  // 16
        load_stage_kk(sb, gA, gB, HID_, HID_, 0, tid);
        CP_COMMIT();
        load_stage_kk(sb + STAGE_KK, gA, gB, HID_, HID_, 32, tid);
        CP_COMMIT();
        int slot = 0;
        #pragma unroll 1
        for (int c = 0; c < NC; c++) {
            if (c < NC - 1) CP_WAIT1(); else CP_WAIT0();
            __syncthreads();
            if (c + 2 < NC) {
                int ns = slot + 2; if (ns >= NSTAGE) ns -= NSTAGE;
                load_stage_kk(sb + ns * STAGE_KK, gA, gB, HID_, HID_,
                              (c + 2) * 32, tid);
            }
            CP_COMMIT();
            compute_chunk_kk(sb + slot * STAGE_KK, warp_m, warp_n, lane, acc);
            if (++slot == NSTAGE) slot = 0;
        }
    }

    float rsum[4][2];
    #pragma unroll
    for (int i = 0; i < 4; i++) { rsum[i][0] = 0.0f; rsum[i][1] = 0.0f; }

    #pragma unroll
    for (int i = 0; i < 4; i++)
        #pragma unroll
        for (int j = 0; j < 8; j++) {
            int row = blockIdx.x * 128 + warp_m * 64 + i * 16 + (lane >> 2);
            int col = blockIdx.y * 128 + warp_n * 64 + j * 8 + (lane & 3) * 2;
            #pragma unroll
            for (int h = 0; h < 2; h++) {
                float e0 = __expf(acc[i][j][h * 2] * SCALE_);
                float e1 = __expf(acc[i][j][h * 2 + 1] * SCALE_);
                size_t off = ((size_t)b * N_ + row + h * 8) * N_ + col;
                *(uint32_t*)&g_E[off] = pk2h(__float2half(e0), __float2half(e1));
                rsum[i][h] += e0 + e1;
            }
        }

    // quad reduce (lanes sharing a row differ only in lane&3), then atomicAdd
    #pragma unroll
    for (int i = 0; i < 4; i++)
        #pragma unroll
        for (int h = 0; h < 2; h++) {
            float s = rsum[i][h];
            s += __shfl_xor_sync(0xffffffffu, s, 1);
            s += __shfl_xor_sync(0xffffffffu, s, 2);
            if ((lane & 3) == 0) {
                size_t r = (size_t)b * N_ + blockIdx.x * 128
                         + warp_m * 64 + i * 16 + (lane >> 2) + h * 8;
                atomicAdd(&g_Rsum[r], s);
            }
        }
}

// ---------------- kernel 3: O = (E V) / rowsum -------------------------------
__global__ __launch_bounds__(128, 2)
void av_kernel(float* __restrict__ out) {
    extern __shared__ char smem[];
    uint32_t sb = smem_u32(smem);
    const int tid = threadIdx.x, lane = tid & 31, wid = tid >> 5;
    const int warp_m = wid & 1, warp_n = wid >> 1;
    const int b = blockIdx.z;
    const int n0 = blockIdx.y * 128;

    const half* gA = g_E + ((size_t)b * N_ + blockIdx.x * 128) * N_;
    const half* gB = g_V + ((size_t)b * N_) * HID_ + n0;   // rows = tokens(k)

    float acc[4][8][4];
    ACC_ZERO(acc);

    {
        const int NC = N_ / 32;  // 64
        load_stage_av(sb, gA, gB, N_, HID_, 0, tid);
        CP_COMMIT();
        load_stage_av(sb + STAGE_AV, gA, gB, N_, HID_, 32, tid);
        CP_COMMIT();
        int slot = 0;
        #pragma unroll 1
        for (int c = 0; c < NC; c++) {
            if (c < NC - 1) CP_WAIT1(); else CP_WAIT0();
            __syncthreads();
            if (c + 2 < NC) {
                int ns = slot + 2; if (ns >= NSTAGE) ns -= NSTAGE;
                load_stage_av(sb + ns * STAGE_AV, gA, gB, N_, HID_,
                              (c + 2) * 32, tid);
            }
            CP_COMMIT();
            compute_chunk_av(sb + slot * STAGE_AV, warp_m, warp_n, lane, acc);
            if (++slot == NSTAGE) slot = 0;
        }
    }

    float rinv[4][2];
    #pragma unroll
    for (int i = 0; i < 4; i++)
        #pragma unroll
        for (int h = 0; h < 2; h++) {
            size_t r = (size_t)b * N_ + blockIdx.x * 128
                     + warp_m * 64 + i * 16 + (lane >> 2) + h * 8;
            rinv[i][h] = 1.0f / g_Rsum[r];
        }

    #pragma unroll
    for (int i = 0; i < 4; i++)
        #pragma unroll
        for (int j = 0; j < 8; j++) {
            int row = blockIdx.x * 128 + warp_m * 64 + i * 16 + (lane >> 2);
            int col = n0 + warp_n * 64 + j * 8 + (lane & 3) * 2;
            #pragma unroll
            for (int h = 0; h < 2; h++) {
                size_t off = ((size_t)b * N_ + row + h * 8) * HID_ + col;
                float2 v = make_float2(acc[i][j][h * 2] * rinv[i][h],
                                       acc[i][j][h * 2 + 1] * rinv[i][h]);
                *(float2*)&out[off] = v;
            }
        }
}

// ---------------- launcher ---------------------------------------------------
extern "C" void kernel_launch(void* const* d_in, const int* in_sizes, int n_in,
                              void* d_out, int out_size) {
    const float* patches   = (const float*)d_in[0];
    const float* positions = (const float*)d_in[1];
    const float* Wq = (const float*)d_in[2];
    const float* bq = (const float*)d_in[3];
    const float* Wk = (const float*)d_in[4];
    const float* bk = (const float*)d_in[5];
    const float* Wv = (const float*)d_in[6];
    const float* bv = (const float*)d_in[7];
    float* out = (float*)d_out;

    cudaFuncSetAttribute(qkv_kernel,   cudaFuncAttributeMaxDynamicSharedMemorySize, SMEM_KK);
    cudaFuncSetAttribute(score_kernel, cudaFuncAttributeMaxDynamicSharedMemorySize, SMEM_KK);
    cudaFuncSetAttribute(av_kernel,    cudaFuncAttributeMaxDynamicSharedMemorySize, SMEM_AV);

    dim3 gw(HID_ / 32, DIN_ / 32, 3);  // 16 x 26 x 3
    wsplit_kernel<<<gw, dim3(32, 32)>>>(Wq, Wk, Wv);

    xsplit_kernel<<<M_TOT, 208>>>(patches, positions);
    zero_rsum_kernel<<<M_TOT / 256, 256>>>();

    dim3 g1(M_TOT / 128, HID_ / 128, 3);  // 128 x 4 x 3
    qkv_kernel<<<g1, 128, SMEM_KK>>>(bq, bk, bv);

    dim3 g2(N_ / 128, N_ / 128, B_);      // 16 x 16 x 8
    score_kernel<<<g2, 128, SMEM_KK>>>();

    dim3 g3(N_ / 128, HID_ / 128, B_);    // 16 x 4 x 8
    av_kernel<<<g3, 128, SMEM_AV>>>(out);
}

// round 16
// speedup vs baseline: 1.3321x; 1.0419x over previous
#include <cuda_runtime.h>
#include <cuda_bf16.h>
#include <cuda_fp16.h>
#include <cstdint>

#define B_      8
#define N_      2048
#define PATCH_  768
#define POS_    64
#define DIN_    832
#define HID_    512
#define M_TOT   (B_ * N_)
#define SCALE_  0.04419417382415922f

// smem tile geometry: CTA tile 128x128, warp tile 64x64 (4 warps, 2x2)
#define LDA_B   80                      // padded row bytes (64 data + 16 pad)
#define LDV_B   272                     // padded row for 128-wide KN tile
#define TILE_A_B 10240                  // 128 * 80
#define TILE_V_B 8704                   // 32 * 272
#define STAGE_KK (2 * TILE_A_B)         // 20480: A + B tiles (both K-major)
#define STAGE_KN (TILE_A_B + TILE_V_B)  // 18944: A (K-major) + B (KN layout)
#define NSTAGE  4
#define SMEM_KK (NSTAGE * STAGE_KK)     // 81920 -> 2 CTAs/SM
#define SMEM_KN (NSTAGE * STAGE_KN)     // 75776 -> 2 CTAs/SM

// ---------------- scratch (static device memory; no allocations) ------------
__device__ __align__(16) half  g_X[(size_t)M_TOT * DIN_];           // fp16 concat input
__device__ __align__(16) half  g_W[(size_t)3 * DIN_ * HID_];        // fp16 W [w][k][n]
__device__ __align__(16) half  g_Q[(size_t)M_TOT * HID_];
__device__ __align__(16) half  g_K[(size_t)M_TOT * HID_];
__device__ __align__(16) half  g_V[(size_t)M_TOT * HID_];
__device__ __align__(16) half  g_E[(size_t)B_ * N_ * N_];           // exp(scores), fp16
__device__ __align__(16) float g_Rsum[(size_t)M_TOT];               // row sums (atomic)

// ---------------- PTX helpers ------------------------------------------------
__device__ __forceinline__ uint32_t smem_u32(const void* p) {
    uint32_t a;
    asm("{ .reg .u64 t; cvta.to.shared.u64 t, %1; cvt.u32.u64 %0, t; }" : "=r"(a) : "l"(p));
    return a;
}
__device__ __forceinline__ void cp16(uint32_t dst, const void* src) {
    asm volatile("cp.async.cg.shared.global [%0], [%1], 16;"
                 :: "r"(dst), "l"(__cvta_generic_to_global(src)));
}
#define CP_COMMIT() asm volatile("cp.async.commit_group;" ::: "memory")
#define CP_WAIT2()  asm volatile("cp.async.wait_group 2;" ::: "memory")
#define CP_WAIT0()  asm volatile("cp.async.wait_group 0;" ::: "memory")

__device__ __forceinline__ void ldm_x4(uint32_t* r, uint32_t addr) {
    asm volatile("ldmatrix.sync.aligned.m8n8.x4.shared.b16 {%0,%1,%2,%3}, [%4];"
                 : "=r"(r[0]), "=r"(r[1]), "=r"(r[2]), "=r"(r[3]) : "r"(addr));
}
__device__ __forceinline__ void ldm_x4t(uint32_t* r, uint32_t addr) {
    asm volatile("ldmatrix.sync.aligned.m8n8.x4.trans.shared.b16 {%0,%1,%2,%3}, [%4];"
                 : "=r"(r[0]), "=r"(r[1]), "=r"(r[2]), "=r"(r[3]) : "r"(addr));
}
__device__ __forceinline__ void mma_f16(float* c, const uint32_t* a, const uint32_t* b) {
    asm volatile("mma.sync.aligned.m16n8k16.row.col.f32.f16.f16.f32 "
                 "{%0,%1,%2,%3}, {%4,%5,%6,%7}, {%8,%9}, {%0,%1,%2,%3};"
                 : "+f"(c[0]), "+f"(c[1]), "+f"(c[2]), "+f"(c[3])
                 : "r"(a[0]), "r"(a[1]), "r"(a[2]), "r"(a[3]), "r"(b[0]), "r"(b[1]));
}
__device__ __forceinline__ uint32_t pk2h(half a, half b) {
    return (uint32_t)__half_as_ushort(a) | ((uint32_t)__half_as_ushort(b) << 16);
}

// ---------------- stage loaders (128 threads) ---------------------------------
// kk: A[128][32] + B[128][32], fp16, both K-major
__device__ __forceinline__ void load_stage_kk(uint32_t sb,
        const half* gA, const half* gB, int ldA, int ldB, int k0, int tid) {
    #pragma unroll
    for (int r = 0; r < 4; r++) {
        int i = tid + 128 * r;   // 0..511
        int row = i >> 2, seg = i & 3;
        uint32_t doff = (uint32_t)(row * LDA_B + seg * 16);
        cp16(sb + doff,            gA + (size_t)row * ldA + k0 + seg * 8);
        cp16(sb + TILE_A_B + doff, gB + (size_t)row * ldB + k0 + seg * 8);
    }
}

// kn: A[128][32] (K-major) + B[32][128] (KN layout; gB pre-offset to col n0)
__device__ __forceinline__ void load_stage_kn(uint32_t sb,
        const half* gA, const half* gB, int ldA, int ldB, int k0, int tid) {
    #pragma unroll
    for (int r = 0; r < 4; r++) {
        int i = tid + 128 * r;
        {
            int row = i >> 2, seg = i & 3;
            cp16(sb + (uint32_t)(row * LDA_B + seg * 16),
                 gA + (size_t)row * ldA + k0 + seg * 8);
        }
        {
            int row = i >> 4, seg = i & 15;  // row 0..31
            cp16(sb + TILE_A_B + (uint32_t)(row * LDV_B + seg * 16),
                 gB + (size_t)(k0 + row) * ldB + seg * 8);
        }
    }
}

// ---------------- compute: one K=32 chunk, 64x64 warp tile, fp16 -------------
__device__ __forceinline__ void compute_chunk_kk(uint32_t sb, int warp_m, int warp_n,
                                                 int lane, float acc[4][8][4]) {
    const int g = lane >> 3;
    uint32_t a[2][4][4], b[2][4][4];
    #pragma unroll
    for (int ks = 0; ks < 2; ks++) {
        const int kc = ks * 16;
        #pragma unroll
        for (int i = 0; i < 4; i++) {
            uint32_t addr = sb + (uint32_t)((warp_m * 64 + i * 16 + (lane & 15)) * LDA_B
                                            + (kc + (lane >> 4) * 8) * 2);
            ldm_x4(a[ks][i], addr);
        }
        #pragma unroll
        for (int jj = 0; jj < 4; jj++) {
            int brow = warp_n * 64 + jj * 16 + ((g & 2) ? 8 : 0) + (lane & 7);
            int bcol = kc + (g & 1) * 8;
            ldm_x4(b[ks][jj], sb + TILE_A_B + (uint32_t)(brow * LDA_B + bcol * 2));
        }
    }
    #pragma unroll
    for (int ks = 0; ks < 2; ks++)
        #pragma unroll
        for (int jj = 0; jj < 4; jj++)
            #pragma unroll
            for (int i = 0; i < 4; i++) {
                mma_f16(acc[i][jj * 2],     a[ks][i], b[ks][jj]);
                mma_f16(acc[i][jj * 2 + 1], a[ks][i], b[ks][jj] + 2);
            }
}

// kn: B in KN layout (trans ldmatrix)
__device__ __forceinline__ void compute_chunk_kn(uint32_t sb, int warp_m, int warp_n,
                                                 int lane, float acc[4][8][4]) {
    const int g = lane >> 3;
    uint32_t a[2][4][4], b[2][4][4];
    #pragma unroll
    for (int ks = 0; ks < 2; ks++) {
        const int kc = ks * 16;
        #pragma unroll
        for (int i = 0; i < 4; i++) {
            uint32_t addr = sb + (uint32_t)((warp_m * 64 + i * 16 + (lane & 15)) * LDA_B
                                            + (kc + (lane >> 4) * 8) * 2);
            ldm_x4(a[ks][i], addr);
        }
        #pragma unroll
        for (int jj = 0; jj < 4; jj++) {
            int brow = kc + (g & 1) * 8 + (lane & 7);
            int bcol = warp_n * 64 + jj * 16 + ((g & 2) ? 8 : 0);
            ldm_x4t(b[ks][jj], sb + TILE_A_B + (uint32_t)(brow * LDV_B + bcol * 2));
        }
    }
    #pragma unroll
    for (int ks = 0; ks < 2; ks++)
        #pragma unroll
        for (int jj = 0; jj < 4; jj++)
            #pragma unroll
            for (int i = 0; i < 4; i++) {
                mma_f16(acc[i][jj * 2],     a[ks][i], b[ks][jj]);
                mma_f16(acc[i][jj * 2 + 1], a[ks][i], b[ks][jj] + 2);
            }
}

#define ACC_ZERO(acc)                                   \
    _Pragma("unroll")                                   \
    for (int _i = 0; _i < 4; _i++)                      \
        _Pragma("unroll")                               \
        for (int _j = 0; _j < 8; _j++)                  \
            _Pragma("unroll")                           \
            for (int _r = 0; _r < 4; _r++) acc[_i][_j][_r] = 0.0f;

// 4-stage ring mainloop: 3 loads in flight, one __syncthreads per chunk.
#define PIPE4(NC, LOADFN, CHUNKFN, STAGE, ldA, ldB)                           \
    LOADFN(sb, gA, gB, ldA, ldB, 0, tid);                                     \
    CP_COMMIT();                                                              \
    LOADFN(sb + STAGE, gA, gB, ldA, ldB, 32, tid);                            \
    CP_COMMIT();                                                              \
    LOADFN(sb + 2 * STAGE, gA, gB, ldA, ldB, 64, tid);                        \
    CP_COMMIT();                                                              \
    int slot = 0;                                                             \
    _Pragma("unroll 1")                                                       \
    for (int c = 0; c < (NC); c++) {                                          \
        if (c < (NC) - 1) CP_WAIT2(); else CP_WAIT0();                        \
        __syncthreads();                                                      \
        if (c + 3 < (NC)) {                                                   \
            int ns = slot + 3; if (ns >= NSTAGE) ns -= NSTAGE;                \
            LOADFN(sb + ns * STAGE, gA, gB, ldA, ldB, (c + 3) * 32, tid);     \
        }                                                                     \
        CP_COMMIT();                                                          \
        CHUNKFN(sb + slot * STAGE, warp_m, warp_n, lane, acc);                \
        if (++slot == NSTAGE) slot = 0;                                       \
    }

// ---------------- prep: fp16 X = concat(patches, positions) ------------------
__global__ void xsplit_kernel(const float* __restrict__ patches,
                              const float* __restrict__ positions) {
    const size_t m = blockIdx.x;
    const int t = threadIdx.x;  // 208 threads, 4 elems each
    const float* src = (t < 192) ? patches + m * PATCH_ + t * 4
                                 : positions + m * POS_ + (t - 192) * 4;
    float4 v = *(const float4*)src;
    uint2 hh = make_uint2(pk2h(__float2half(v.x), __float2half(v.y)),
                          pk2h(__float2half(v.z), __float2half(v.w)));
    *(uint2*)&g_X[m * DIN_ + t * 4] = hh;
}

// ---------------- prep: cast W to fp16 (no transpose) ------------------------
__global__ void wcast_kernel(const float* __restrict__ Wq,
                             const float* __restrict__ Wk,
                             const float* __restrict__ Wv) {
    const size_t elems = (size_t)DIN_ * HID_;
    size_t i = (size_t)blockIdx.x * blockDim.x + threadIdx.x;  // over 4-elem groups
    size_t base = i * 4;
    int which = (int)(base / elems);
    size_t off = base - (size_t)which * elems;
    const float* W = (which == 0) ? Wq : (which == 1) ? Wk : Wv;
    float4 v = *(const float4*)(W + off);
    uint2 hh = make_uint2(pk2h(__float2half(v.x), __float2half(v.y)),
                          pk2h(__float2half(v.z), __float2half(v.w)));
    *(uint2*)&g_W[(size_t)which * elems + off] = hh;
}

__global__ void zero_rsum_kernel() {
    g_Rsum[blockIdx.x * 256 + threadIdx.x] = 0.0f;
}

// ---------------- kernel 1: QKV projection (fp16, B = W in KN layout) --------
__global__ __launch_bounds__(128, 2)
void qkv_kernel(const float* __restrict__ bq, const float* __restrict__ bk,
                const float* __restrict__ bv) {
    extern __shared__ char smem[];
    uint32_t sb = smem_u32(smem);
    const int tid = threadIdx.x, lane = tid & 31, wid = tid >> 5;
    const int warp_m = wid & 1, warp_n = wid >> 1;
    const int which = blockIdx.z;
    const size_t m0 = (size_t)blockIdx.x * 128;
    const int n0 = blockIdx.y * 128;

    const half* gA = g_X + m0 * DIN_;
    const half* gB = g_W + (size_t)which * DIN_ * HID_ + n0;  // rows = k, cols = n

    float acc[4][8][4];
    ACC_ZERO(acc);

    PIPE4(DIN_ / 32, load_stage_kn, compute_chunk_kn, STAGE_KN, DIN_, HID_);

    const float* bias = (which == 0) ? bq : (which == 1) ? bk : bv;
    half* dst = (which == 0) ? g_Q : (which == 1) ? g_K : g_V;
    #pragma unroll
    for (int i = 0; i < 4; i++)
        #pragma unroll
        for (int j = 0; j < 8; j++) {
            int row = warp_m * 64 + i * 16 + (lane >> 2);
            int col = n0 + warp_n * 64 + j * 8 + (lane & 3) * 2;
            float b0 = bias[col], b1 = bias[col + 1];
            #pragma unroll
            for (int h = 0; h < 2; h++) {
                size_t r = m0 + row + h * 8;
                *(uint32_t*)&dst[r * HID_ + col] =
                    pk2h(__float2half(acc[i][j][h * 2] + b0),
                         __float2half(acc[i][j][h * 2 + 1] + b1));
            }
        }
}

// ---------------- kernel 2: E = exp(QK^T*scale), fp16 + fused row sums -------
__global__ __launch_bounds__(128, 2)
void score_kernel() {
    extern __shared__ char smem[];
    uint32_t sb = smem_u32(smem);
    const int tid = threadIdx.x, lane = tid & 31, wid = tid >> 5;
    const int warp_m = wid & 1, warp_n = wid >> 1;
    const int b = blockIdx.z;
    const size_t m0 = (size_t)b * N_ + blockIdx.x * 128;
    const size_t n0 = (size_t)b * N_ + blockIdx.y * 128;

    const half* gA = g_Q + m0 * HID_;
    const half* gB = g_K + n0 * HID_;

    float acc[4][8][4];
    ACC_ZERO(acc);

    PIPE4(HID_ / 32, load_stage_kk, compute_chunk_kk, STAGE_KK, HID_, HID_);

    float rsum[4][2];
    #pragma unroll
    for (int i = 0; i < 4; i++) { rsum[i][0] = 0.0f; rsum[i][1] = 0.0f; }

    #pragma unroll
    for (int i = 0; i < 4; i++)
        #pragma unroll
        for (int j = 0; j < 8; j++) {
            int row = blockIdx.x * 128 + warp_m * 64 + i * 16 + (lane >> 2);
            int col = blockIdx.y * 128 + warp_n * 64 + j * 8 + (lane & 3) * 2;
            #pragma unroll
            for (int h = 0; h < 2; h++) {
                float e0 = __expf(acc[i][j][h * 2] * SCALE_);
                float e1 = __expf(acc[i][j][h * 2 + 1] * SCALE_);
                size_t off = ((size_t)b * N_ + row + h * 8) * N_ + col;
                *(uint32_t*)&g_E[off] = pk2h(__float2half(e0), __float2half(e1));
                rsum[i][h] += e0 + e1;
            }
        }

    // quad reduce (lanes sharing a row differ only in lane&3), then atomicAdd
    #pragma unroll
    for (int i = 0; i < 4; i++)
        #pragma unroll
        for (int h = 0; h < 2; h++) {
            float s = rsum[i][h];
            s += __shfl_xor_sync(0xffffffffu, s, 1);
            s += __shfl_xor_sync(0xffffffffu, s, 2);
            if ((lane & 3) == 0) {
                size_t r = (size_t)b * N_ + blockIdx.x * 128
                         + warp_m * 64 + i * 16 + (lane >> 2) + h * 8;
                atomicAdd(&g_Rsum[r], s);
            }
        }
}

// ---------------- kernel 3: O = (E V) / rowsum -------------------------------
__global__ __launch_bounds__(128, 2)
void av_kernel(float* __restrict__ out) {
    extern __shared__ char smem[];
    uint32_t sb = smem_u32(smem);
    const int tid = threadIdx.x, lane = tid & 31, wid = tid >> 5;
    const int warp_m = wid & 1, warp_n = wid >> 1;
    const int b = blockIdx.z;
    const int n0 = blockIdx.y * 128;

    const half* gA = g_E + ((size_t)b * N_ + blockIdx.x * 128) * N_;
    const half* gB = g_V + ((size_t)b * N_) * HID_ + n0;   // rows = tokens(k)

    float acc[4][8][4];
    ACC_ZERO(acc);

    PIPE4(N_ / 32, load_stage_kn, compute_chunk_kn, STAGE_KN, N_, HID_);

    float rinv[4][2];
    #pragma unroll
    for (int i = 0; i < 4; i++)
        #pragma unroll
        for (int h = 0; h < 2; h++) {
            size_t r = (size_t)b * N_ + blockIdx.x * 128
                     + warp_m * 64 + i * 16 + (lane >> 2) + h * 8;
            rinv[i][h] = 1.0f / g_Rsum[r];
        }

    #pragma unroll
    for (int i = 0; i < 4; i++)
        #pragma unroll
        for (int j = 0; j < 8; j++) {
            int row = blockIdx.x * 128 + warp_m * 64 + i * 16 + (lane >> 2);
            int col = n0 + warp_n * 64 + j * 8 + (lane & 3) * 2;
            #pragma unroll
            for (int h = 0; h < 2; h++) {
                size_t off = ((size_t)b * N_ + row + h * 8) * HID_ + col;
                float2 v = make_float2(acc[i][j][h * 2] * rinv[i][h],
                                       acc[i][j][h * 2 + 1] * rinv[i][h]);
                *(float2*)&out[off] = v;
            }
        }
}

// ---------------- launcher ---------------------------------------------------
extern "C" void kernel_launch(void* const* d_in, const int* in_sizes, int n_in,
                              void* d_out, int out_size) {
    const float* patches   = (const float*)d_in[0];
    const float* positions = (const float*)d_in[1];
    const float* Wq = (const float*)d_in[2];
    const float* bq = (const float*)d_in[3];
    const float* Wk = (const float*)d_in[4];
    const float* bk = (const float*)d_in[5];
    const float* Wv = (const float*)d_in[6];
    const float* bv = (const float*)d_in[7];
    float* out = (float*)d_out;

    cudaFuncSetAttribute(qkv_kernel,   cudaFuncAttributeMaxDynamicSharedMemorySize, SMEM_KN);
    cudaFuncSetAttribute(score_kernel, cudaFuncAttributeMaxDynamicSharedMemorySize, SMEM_KK);
    cudaFuncSetAttribute(av_kernel,    cudaFuncAttributeMaxDynamicSharedMemorySize, SMEM_KN);

    // 3 * 832 * 512 / 4 elems per thread / 256 threads = 1248 blocks
    wcast_kernel<<<1248, 256>>>(Wq, Wk, Wv);
    xsplit_kernel<<<M_TOT, 208>>>(patches, positions);
    zero_rsum_kernel<<<M_TOT / 256, 256>>>();

    dim3 g1(M_TOT / 128, HID_ / 128, 3);  // 128 x 4 x 3
    qkv_kernel<<<g1, 128, SMEM_KN>>>(bq, bk, bv);

    dim3 g2(N_ / 128, N_ / 128, B_);      // 16 x 16 x 8
    score_kernel<<<g2, 128, SMEM_KK>>>();

    dim3 g3(N_ / 128, HID_ / 128, B_);    // 16 x 4 x 8
    av_kernel<<<g3, 128, SMEM_KN>>>(out);
}